// round 2
// baseline (speedup 1.0000x reference)
#include <cuda_runtime.h>
#include <math.h>

#define B_   64
#define C_   8
#define H_   256
#define W_   256
#define N_   200
#define NT   (B_ * N_)          // 12800 targets
#define HW   (H_ * W_)          // 65536
#define NUM_CLASSES 3

#define THREADS 256
#define BLOCKS  ((NT + THREADS - 1) / THREADS)   // 50

// Per-block partials (always fully overwritten each run) + ticket counter.
__device__ float        g_part[BLOCKS][3];
__device__ unsigned int g_count;   // zero-initialized at load; reset by last block each run

__device__ __forceinline__ float softplus_f(float x) {
    return fmaxf(x, 0.0f) + log1pf(expf(-fabsf(x)));
}

__device__ __forceinline__ float warp_sum(float v) {
    #pragma unroll
    for (int off = 16; off > 0; off >>= 1)
        v += __shfl_xor_sync(0xFFFFFFFFu, v, off);
    return v;
}

__global__ void __launch_bounds__(THREADS) yolo_fused_kernel(
    const float* __restrict__ pred,
    const float* __restrict__ targets,
    float* __restrict__ out)
{
    int i = blockIdx.x * blockDim.x + threadIdx.x;

    float bbox = 0.0f, obj = 0.0f, clsl = 0.0f;

    if (i < NT) {
        int b = i / N_;
        const float* t = targets + (size_t)i * 5;
        float cid = t[0];
        float c0 = t[1], c1 = t[2], c2 = t[3], c3 = t[4];

        float csum = ((c0 + c1) + c2) + c3;
        int xp = (int)(c0 * (float)W_);
        int yp = (int)(c1 * (float)H_);
        bool valid = (cid >= 0.0f) && (csum > 0.0f);
        bool inb = (xp >= 0) && (xp < W_) && (yp >= 0) && (yp < H_);

        if (valid && inb) {
            int xs = min(max(xp, 0), W_ - 1);
            int ys = min(max(yp, 0), H_ - 1);
            const float* base = pred + ((size_t)b * C_) * HW + (size_t)ys * W_ + xs;

            float p[C_];
            #pragma unroll
            for (int c = 0; c < C_; c++)
                p[c] = __ldg(base + (size_t)c * HW);   // 8 independent loads, MLP=8

            float d0 = p[0] - c0, d1 = p[1] - c1, d2 = p[2] - c2, d3 = p[3] - c3;
            bbox = 0.25f * (d0 * d0 + d1 * d1 + d2 * d2 + d3 * d3);

            obj = softplus_f(-p[4]);   // bce(p4, 1)

            int k = (int)fmaxf(cid, 0.0f);
            float s = 0.0f;
            #pragma unroll
            for (int c = 0; c < NUM_CLASSES; c++) {
                float l = p[5 + c];
                float z = (c == k) ? 1.0f : 0.0f;
                s += softplus_f(l) - l * z;
            }
            clsl = s * (1.0f / 3.0f);
        }
    }

    // Intra-block reduction: warp shuffle, then 8 warp-leaders via shared.
    __shared__ float sb[THREADS / 32], so[THREADS / 32], sc[THREADS / 32];
    int lane = threadIdx.x & 31;
    int wid  = threadIdx.x >> 5;

    bbox = warp_sum(bbox);
    obj  = warp_sum(obj);
    clsl = warp_sum(clsl);
    if (lane == 0) { sb[wid] = bbox; so[wid] = obj; sc[wid] = clsl; }
    __syncthreads();

    if (wid == 0) {
        float vb = (lane < THREADS / 32) ? sb[lane] : 0.0f;
        float vo = (lane < THREADS / 32) ? so[lane] : 0.0f;
        float vc = (lane < THREADS / 32) ? sc[lane] : 0.0f;
        vb = warp_sum(vb); vo = warp_sum(vo); vc = warp_sum(vc);
        if (lane == 0) {
            g_part[blockIdx.x][0] = vb;
            g_part[blockIdx.x][1] = vo;
            g_part[blockIdx.x][2] = vc;
        }
    }

    // Last-block finalize
    __shared__ bool is_last;
    __threadfence();
    if (threadIdx.x == 0) {
        unsigned int old = atomicAdd(&g_count, 1u);
        is_last = (old == (unsigned int)(gridDim.x - 1));
    }
    __syncthreads();

    if (is_last && threadIdx.x == 0) {
        g_count = 0;   // reset for next graph replay
        double bs = 0.0, os = 0.0, cs = 0.0;
        volatile float (*part)[3] = g_part;
        #pragma unroll 1
        for (int j = 0; j < BLOCKS; j++) {
            bs += (double)part[j][0];
            os += (double)part[j][1];
            cs += (double)part[j][2];
        }
        double total = 0.05 * bs + 1.0 * os + 0.5 * cs;
        out[0] = (float)total;
        out[1] = (float)bs;
        out[2] = (float)os;
        out[3] = (float)cs;
    }
}

extern "C" void kernel_launch(void* const* d_in, const int* in_sizes, int n_in,
                              void* d_out, int out_size)
{
    const float* pred    = (const float*)d_in[0];
    const float* targets = (const float*)d_in[1];
    float* out = (float*)d_out;

    yolo_fused_kernel<<<BLOCKS, THREADS>>>(pred, targets, out);
}

// round 3
// speedup vs baseline: 2.7317x; 2.7317x over previous
#include <cuda_runtime.h>
#include <math.h>

#define B_   64
#define C_   8
#define H_   256
#define W_   256
#define N_   200
#define NT   (B_ * N_)          // 12800 targets
#define HW   (H_ * W_)          // 65536
#define NUM_CLASSES 3

#define THREADS 128
#define BLOCKS  ((NT + THREADS - 1) / THREADS)   // 100

// Per-block partials (fully overwritten each run) + ticket counter.
__device__ float        g_part[BLOCKS][3];
__device__ unsigned int g_count;   // zero at load; reset by last block each run

__device__ __forceinline__ float softplus_f(float x) {
    return fmaxf(x, 0.0f) + log1pf(expf(-fabsf(x)));
}

__device__ __forceinline__ float warp_sum_f(float v) {
    #pragma unroll
    for (int off = 16; off > 0; off >>= 1)
        v += __shfl_xor_sync(0xFFFFFFFFu, v, off);
    return v;
}

__device__ __forceinline__ double warp_sum_d(double v) {
    #pragma unroll
    for (int off = 16; off > 0; off >>= 1)
        v += __shfl_xor_sync(0xFFFFFFFFu, v, off);
    return v;
}

__global__ void __launch_bounds__(THREADS) yolo_fused_kernel(
    const float* __restrict__ pred,
    const float* __restrict__ targets,
    float* __restrict__ out)
{
    int i = blockIdx.x * blockDim.x + threadIdx.x;

    float bbox = 0.0f, obj = 0.0f, clsl = 0.0f;

    if (i < NT) {
        int b = i / N_;
        const float* t = targets + (size_t)i * 5;
        float cid = t[0];
        float c0 = t[1], c1 = t[2], c2 = t[3], c3 = t[4];

        float csum = ((c0 + c1) + c2) + c3;
        int xp = (int)(c0 * (float)W_);
        int yp = (int)(c1 * (float)H_);
        bool valid = (cid >= 0.0f) && (csum > 0.0f);
        bool inb = (xp >= 0) && (xp < W_) && (yp >= 0) && (yp < H_);

        if (valid && inb) {
            int xs = min(max(xp, 0), W_ - 1);
            int ys = min(max(yp, 0), H_ - 1);
            const float* base = pred + ((size_t)b * C_) * HW + (size_t)ys * W_ + xs;

            float p[C_];
            #pragma unroll
            for (int c = 0; c < C_; c++)
                p[c] = __ldg(base + (size_t)c * HW);   // 8 independent loads, MLP=8

            float d0 = p[0] - c0, d1 = p[1] - c1, d2 = p[2] - c2, d3 = p[3] - c3;
            bbox = 0.25f * (d0 * d0 + d1 * d1 + d2 * d2 + d3 * d3);

            obj = softplus_f(-p[4]);   // bce(p4, 1)

            int k = (int)fmaxf(cid, 0.0f);
            float s = 0.0f;
            #pragma unroll
            for (int c = 0; c < NUM_CLASSES; c++) {
                float l = p[5 + c];
                float z = (c == k) ? 1.0f : 0.0f;
                s += softplus_f(l) - l * z;
            }
            clsl = s * (1.0f / 3.0f);
        }
    }

    // Intra-block reduction: warp shuffle, then 4 warp-leaders via shared.
    __shared__ float sb[THREADS / 32], so[THREADS / 32], sc[THREADS / 32];
    int lane = threadIdx.x & 31;
    int wid  = threadIdx.x >> 5;

    bbox = warp_sum_f(bbox);
    obj  = warp_sum_f(obj);
    clsl = warp_sum_f(clsl);
    if (lane == 0) { sb[wid] = bbox; so[wid] = obj; sc[wid] = clsl; }
    __syncthreads();

    if (wid == 0) {
        float vb = (lane < THREADS / 32) ? sb[lane] : 0.0f;
        float vo = (lane < THREADS / 32) ? so[lane] : 0.0f;
        float vc = (lane < THREADS / 32) ? sc[lane] : 0.0f;
        vb = warp_sum_f(vb); vo = warp_sum_f(vo); vc = warp_sum_f(vc);
        if (lane == 0) {
            g_part[blockIdx.x][0] = vb;
            g_part[blockIdx.x][1] = vo;
            g_part[blockIdx.x][2] = vc;
        }
    }

    // Last-block finalize (parallel, deterministic)
    __shared__ bool is_last;
    __threadfence();
    if (threadIdx.x == 0) {
        unsigned int old = atomicAdd(&g_count, 1u);
        is_last = (old == (unsigned int)(gridDim.x - 1));
    }
    __syncthreads();

    if (is_last && wid == 0) {
        // Warp 0: lane-strided gather of all partials (concurrent loads),
        // fixed-order shuffle tree in double -> deterministic.
        double bs = 0.0, os = 0.0, cs = 0.0;
        #pragma unroll
        for (int j = lane; j < BLOCKS; j += 32) {
            bs += (double)g_part[j][0];
            os += (double)g_part[j][1];
            cs += (double)g_part[j][2];
        }
        bs = warp_sum_d(bs);
        os = warp_sum_d(os);
        cs = warp_sum_d(cs);
        if (lane == 0) {
            g_count = 0;   // reset for next graph replay
            double total = 0.05 * bs + 1.0 * os + 0.5 * cs;
            out[0] = (float)total;
            out[1] = (float)bs;
            out[2] = (float)os;
            out[3] = (float)cs;
        }
    }
}

extern "C" void kernel_launch(void* const* d_in, const int* in_sizes, int n_in,
                              void* d_out, int out_size)
{
    const float* pred    = (const float*)d_in[0];
    const float* targets = (const float*)d_in[1];
    float* out = (float*)d_out;

    yolo_fused_kernel<<<BLOCKS, THREADS>>>(pred, targets, out);
}

// round 4
// speedup vs baseline: 2.8824x; 1.0551x over previous
#include <cuda_runtime.h>
#include <math.h>

#define B_   64
#define C_   8
#define H_   256
#define W_   256
#define N_   200
#define NT   (B_ * N_)          // 12800 targets
#define HW   (H_ * W_)          // 65536
#define NUM_CLASSES 3

#define THREADS 96
#define BLOCKS  148            // one CTA per SM; 148*96 = 14208 >= 12800
#define NWARPS  (THREADS / 32)

// Per-block partials (fully overwritten each run) + ticket counter.
__device__ float        g_part[BLOCKS][3];
__device__ unsigned int g_count;   // zero at load; reset by last block each run

__device__ __forceinline__ float softplus_f(float x) {
    return fmaxf(x, 0.0f) + log1pf(expf(-fabsf(x)));
}

__device__ __forceinline__ float warp_sum_f(float v) {
    #pragma unroll
    for (int off = 16; off > 0; off >>= 1)
        v += __shfl_xor_sync(0xFFFFFFFFu, v, off);
    return v;
}

__device__ __forceinline__ double warp_sum_d(double v) {
    #pragma unroll
    for (int off = 16; off > 0; off >>= 1)
        v += __shfl_xor_sync(0xFFFFFFFFu, v, off);
    return v;
}

__global__ void __launch_bounds__(THREADS) yolo_fused_kernel(
    const float* __restrict__ pred,
    const float* __restrict__ targets,
    float* __restrict__ out)
{
    int i = blockIdx.x * blockDim.x + threadIdx.x;

    float bbox = 0.0f, obj = 0.0f, clsl = 0.0f;

    if (i < NT) {
        int b = i / N_;
        const float* t = targets + (size_t)i * 5;
        float cid = t[0];
        float c0 = t[1], c1 = t[2], c2 = t[3], c3 = t[4];

        float csum = ((c0 + c1) + c2) + c3;
        int xp = (int)(c0 * (float)W_);
        int yp = (int)(c1 * (float)H_);
        bool valid = (cid >= 0.0f) && (csum > 0.0f);
        bool inb = (xp >= 0) && (xp < W_) && (yp >= 0) && (yp < H_);

        if (valid && inb) {
            int xs = min(max(xp, 0), W_ - 1);
            int ys = min(max(yp, 0), H_ - 1);
            const float* base = pred + ((size_t)b * C_) * HW + (size_t)ys * W_ + xs;

            float p[C_];
            #pragma unroll
            for (int c = 0; c < C_; c++)
                p[c] = __ldg(base + (size_t)c * HW);   // 8 independent loads, MLP=8

            float d0 = p[0] - c0, d1 = p[1] - c1, d2 = p[2] - c2, d3 = p[3] - c3;
            bbox = 0.25f * (d0 * d0 + d1 * d1 + d2 * d2 + d3 * d3);

            obj = softplus_f(-p[4]);   // bce(p4, 1)

            int k = (int)fmaxf(cid, 0.0f);
            float s = 0.0f;
            #pragma unroll
            for (int c = 0; c < NUM_CLASSES; c++) {
                float l = p[5 + c];
                float z = (c == k) ? 1.0f : 0.0f;
                s += softplus_f(l) - l * z;
            }
            clsl = s * (1.0f / 3.0f);
        }
    }

    // Intra-block reduction: warp shuffle, then warp-leaders via shared.
    __shared__ float sb[NWARPS], so[NWARPS], sc[NWARPS];
    int lane = threadIdx.x & 31;
    int wid  = threadIdx.x >> 5;

    bbox = warp_sum_f(bbox);
    obj  = warp_sum_f(obj);
    clsl = warp_sum_f(clsl);
    if (lane == 0) { sb[wid] = bbox; so[wid] = obj; sc[wid] = clsl; }
    __syncthreads();

    if (wid == 0) {
        float vb = (lane < NWARPS) ? sb[lane] : 0.0f;
        float vo = (lane < NWARPS) ? so[lane] : 0.0f;
        float vc = (lane < NWARPS) ? sc[lane] : 0.0f;
        vb = warp_sum_f(vb); vo = warp_sum_f(vo); vc = warp_sum_f(vc);
        if (lane == 0) {
            g_part[blockIdx.x][0] = vb;
            g_part[blockIdx.x][1] = vo;
            g_part[blockIdx.x][2] = vc;
        }
    }

    // Last-block finalize (parallel, deterministic). Only tid 0 wrote g_part,
    // so only tid 0 needs the fence before publishing via the counter.
    __shared__ bool is_last;
    if (threadIdx.x == 0) {
        __threadfence();
        unsigned int old = atomicAdd(&g_count, 1u);
        is_last = (old == (unsigned int)(gridDim.x - 1));
    }
    __syncthreads();

    if (is_last && wid == 0) {
        double bs = 0.0, os = 0.0, cs = 0.0;
        #pragma unroll
        for (int j = lane; j < BLOCKS; j += 32) {
            bs += (double)g_part[j][0];
            os += (double)g_part[j][1];
            cs += (double)g_part[j][2];
        }
        bs = warp_sum_d(bs);
        os = warp_sum_d(os);
        cs = warp_sum_d(cs);
        if (lane == 0) {
            g_count = 0;   // reset for next graph replay
            double total = 0.05 * bs + 1.0 * os + 0.5 * cs;
            out[0] = (float)total;
            out[1] = (float)bs;
            out[2] = (float)os;
            out[3] = (float)cs;
        }
    }
}

extern "C" void kernel_launch(void* const* d_in, const int* in_sizes, int n_in,
                              void* d_out, int out_size)
{
    const float* pred    = (const float*)d_in[0];
    const float* targets = (const float*)d_in[1];
    float* out = (float*)d_out;

    yolo_fused_kernel<<<BLOCKS, THREADS>>>(pred, targets, out);
}